// round 1
// baseline (speedup 1.0000x reference)
#include <cuda_runtime.h>
#include <math.h>

// Problem constants (fixed shapes from reference)
#define B_  4
#define T_  2048
#define C_  1024
#define H_  16
#define DK_ 64

// Scratch (no cudaMalloc allowed) — __device__ globals
__device__ float g_q[(size_t)B_ * H_ * T_ * DK_];   // [B,H,T,dk]
__device__ float g_k[(size_t)B_ * H_ * T_ * DK_];
__device__ float g_v[(size_t)B_ * H_ * T_ * DK_];
__device__ float g_y[(size_t)B_ * T_ * C_];         // attention output, [B,T,C]

// ---------------------------------------------------------------------------
// SGEMM: C[M,N] = A[M,K] @ W[N,K]^T + bias[N]
// MODE 0: A is g_y (ignore A arg), plain row-major store to C (final proj)
// MODE 1: A is the x input, epilogue scatters qkv into g_q/g_k/g_v [B,H,T,dk]
// 128x128x8 tiles, 256 threads, 8x8 microtile per thread (split 2x2 of 4x4).
// ---------------------------------------------------------------------------
#define BM 128
#define BN 128
#define BK 8

template <int MODE>
__global__ __launch_bounds__(256) void sgemm_tn(
    const float* __restrict__ A, const float* __restrict__ Bw,
    const float* __restrict__ bias, float* __restrict__ C,
    int M, int N, int K)
{
    __shared__ float As[BK][BM + 4];
    __shared__ float Bs[BK][BN + 4];

    const int tid = threadIdx.x;
    const int tm = tid >> 4;          // 0..15
    const int tn = tid & 15;          // 0..15
    const int lr = tid >> 1;          // 0..127 (row loaded)
    const int lc = (tid & 1) * 4;     // 0 or 4  (k offset loaded)

    const float* Abase = (MODE == 0) ? g_y : A;
    const float* Ap = Abase + (size_t)(blockIdx.y * BM + lr) * K + lc;
    const float* Bp = Bw    + (size_t)(blockIdx.x * BN + lr) * K + lc;

    float acc[8][8];
#pragma unroll
    for (int i = 0; i < 8; i++)
#pragma unroll
        for (int j = 0; j < 8; j++) acc[i][j] = 0.f;

    for (int k0 = 0; k0 < K; k0 += BK) {
        float4 a = *(const float4*)(Ap + k0);
        float4 b = *(const float4*)(Bp + k0);
        __syncthreads();   // previous tile fully consumed
        As[lc + 0][lr] = a.x; As[lc + 1][lr] = a.y;
        As[lc + 2][lr] = a.z; As[lc + 3][lr] = a.w;
        Bs[lc + 0][lr] = b.x; Bs[lc + 1][lr] = b.y;
        Bs[lc + 2][lr] = b.z; Bs[lc + 3][lr] = b.w;
        __syncthreads();
#pragma unroll
        for (int k = 0; k < BK; k++) {
            float ar[8], br[8];
            *(float4*)(ar)     = *(const float4*)&As[k][tm * 4];
            *(float4*)(ar + 4) = *(const float4*)&As[k][64 + tm * 4];
            *(float4*)(br)     = *(const float4*)&Bs[k][tn * 4];
            *(float4*)(br + 4) = *(const float4*)&Bs[k][64 + tn * 4];
#pragma unroll
            for (int i = 0; i < 8; i++)
#pragma unroll
                for (int j = 0; j < 8; j++)
                    acc[i][j] = fmaf(ar[i], br[j], acc[i][j]);
        }
    }

    // epilogue
#pragma unroll
    for (int i = 0; i < 8; i++) {
        const int m = blockIdx.y * BM + (i >> 2) * 64 + tm * 4 + (i & 3);
#pragma unroll
        for (int j = 0; j < 8; j++) {
            const int n = blockIdx.x * BN + (j >> 2) * 64 + tn * 4 + (j & 3);
            const float v = acc[i][j] + bias[n];
            if (MODE == 0) {
                C[(size_t)m * N + n] = v;
            } else {
                const int sec = n >> 10;        // 0=q 1=k 2=v
                const int c   = n & 1023;
                const int h   = c >> 6;
                const int d   = c & 63;
                const int bb  = m >> 11;        // token m = b*2048 + t
                const int t   = m & 2047;
                float* dst = (sec == 0) ? g_q : ((sec == 1) ? g_k : g_v);
                dst[((size_t)((bb * H_ + h) * T_ + t)) * DK_ + d] = v;
            }
        }
    }
}

// ---------------------------------------------------------------------------
// Flash attention: one thread per query row, K/V tiles of 64 rows in smem.
// Online softmax with 16-key chunks (amortizes accumulator rescale).
// q pre-scaled by 1/sqrt(dk). Writes g_y in [B,T,C] layout.
// ---------------------------------------------------------------------------
__global__ __launch_bounds__(128) void flash_attn_kernel()
{
    const float scale = 0.125f;  // 1/sqrt(64)
    const int bh   = blockIdx.x;                       // b*H + h
    const int qrow = blockIdx.y * 128 + threadIdx.x;   // query token index

    const float* Qp = g_q + ((size_t)bh * T_ + qrow) * DK_;
    float q[64];
#pragma unroll
    for (int i = 0; i < 16; i++) {
        float4 t4 = *(const float4*)(Qp + 4 * i);
        q[4 * i + 0] = t4.x * scale; q[4 * i + 1] = t4.y * scale;
        q[4 * i + 2] = t4.z * scale; q[4 * i + 3] = t4.w * scale;
    }

    float acc[64];
#pragma unroll
    for (int d = 0; d < 64; d++) acc[d] = 0.f;
    float mrun = -1e30f, l = 0.f;

    __shared__ float Ks[64][64];
    __shared__ float Vs[64][64];
    const float* Kbase = g_k + (size_t)bh * T_ * DK_;
    const float* Vbase = g_v + (size_t)bh * T_ * DK_;

    for (int k0 = 0; k0 < T_; k0 += 64) {
        __syncthreads();
        const float4* Kg = (const float4*)(Kbase + (size_t)k0 * DK_);
        const float4* Vg = (const float4*)(Vbase + (size_t)k0 * DK_);
#pragma unroll
        for (int i = 0; i < 8; i++) {
            ((float4*)Ks)[threadIdx.x + i * 128] = Kg[threadIdx.x + i * 128];
            ((float4*)Vs)[threadIdx.x + i * 128] = Vg[threadIdx.x + i * 128];
        }
        __syncthreads();

#pragma unroll 1
        for (int j0 = 0; j0 < 64; j0 += 16) {
            float s[16];
#pragma unroll
            for (int jj = 0; jj < 16; jj++) {
                const float4* Kr = (const float4*)Ks[j0 + jj];
                float sum = 0.f;
#pragma unroll
                for (int d = 0; d < 16; d++) {
                    float4 kk = Kr[d];
                    sum = fmaf(q[4 * d + 0], kk.x,
                          fmaf(q[4 * d + 1], kk.y,
                          fmaf(q[4 * d + 2], kk.z,
                          fmaf(q[4 * d + 3], kk.w, sum))));
                }
                s[jj] = sum;
            }
            float mnew = mrun;
#pragma unroll
            for (int jj = 0; jj < 16; jj++) mnew = fmaxf(mnew, s[jj]);
            const float corr = __expf(mrun - mnew);
            mrun = mnew;
            l *= corr;
#pragma unroll
            for (int d = 0; d < 64; d++) acc[d] *= corr;
#pragma unroll
            for (int jj = 0; jj < 16; jj++) {
                const float p = __expf(s[jj] - mrun);
                l += p;
                const float4* Vr = (const float4*)Vs[j0 + jj];
#pragma unroll
                for (int d = 0; d < 16; d++) {
                    float4 vv = Vr[d];
                    acc[4 * d + 0] = fmaf(p, vv.x, acc[4 * d + 0]);
                    acc[4 * d + 1] = fmaf(p, vv.y, acc[4 * d + 1]);
                    acc[4 * d + 2] = fmaf(p, vv.z, acc[4 * d + 2]);
                    acc[4 * d + 3] = fmaf(p, vv.w, acc[4 * d + 3]);
                }
            }
        }
    }

    const float inv = 1.f / l;
    const int bb = bh >> 4, h = bh & 15;
    float* Yp = g_y + ((size_t)(bb * T_ + qrow)) * C_ + h * DK_;
#pragma unroll
    for (int i = 0; i < 16; i++) {
        float4 o;
        o.x = acc[4 * i + 0] * inv; o.y = acc[4 * i + 1] * inv;
        o.z = acc[4 * i + 2] * inv; o.w = acc[4 * i + 3] * inv;
        *(float4*)(Yp + 4 * i) = o;
    }
}

// ---------------------------------------------------------------------------
extern "C" void kernel_launch(void* const* d_in, const int* in_sizes, int n_in,
                              void* d_out, int out_size)
{
    const float* x      = (const float*)d_in[0];
    const float* w_attn = (const float*)d_in[1];
    const float* b_attn = (const float*)d_in[2];
    const float* w_proj = (const float*)d_in[3];
    const float* b_proj = (const float*)d_in[4];
    float* out = (float*)d_out;

    const int M = B_ * T_;   // 8192

    // 1) QKV projection with scatter into [B,H,T,dk]
    {
        dim3 grid((3 * C_) / BN, M / BM);
        sgemm_tn<1><<<grid, 256>>>(x, w_attn, b_attn, nullptr, M, 3 * C_, C_);
    }
    // 2) Flash attention -> g_y
    {
        dim3 grid(B_ * H_, T_ / 128);
        flash_attn_kernel<<<grid, 128>>>();
    }
    // 3) Output projection -> d_out
    {
        dim3 grid(C_ / BN, M / BM);
        sgemm_tn<0><<<grid, 256>>>(nullptr, w_proj, b_proj, out, M, C_, C_);
    }
}

// round 3
// speedup vs baseline: 3.4926x; 3.4926x over previous
#include <cuda_runtime.h>
#include <cuda_bf16.h>
#include <cstdint>

typedef __nv_bfloat16 bf16;

#define B_  4
#define T_  2048
#define C_  1024
#define H_  16
#define DK_ 64
#define M_  (B_ * T_)      // 8192
#define KD_ 1024           // GEMM K dim

// ---------------------------------------------------------------------------
// Scratch (static __device__ arrays; no runtime allocation)
// ---------------------------------------------------------------------------
__device__ bf16 g_x_hi[(size_t)M_ * C_],     g_x_lo[(size_t)M_ * C_];
__device__ bf16 g_wa_hi[(size_t)3 * C_ * C_], g_wa_lo[(size_t)3 * C_ * C_];
__device__ bf16 g_wp_hi[(size_t)C_ * C_],     g_wp_lo[(size_t)C_ * C_];
__device__ bf16 g_q_hi[(size_t)M_ * C_], g_q_lo[(size_t)M_ * C_];   // [B,H,T,dk]
__device__ bf16 g_k_hi[(size_t)M_ * C_], g_k_lo[(size_t)M_ * C_];
__device__ bf16 g_v_hi[(size_t)M_ * C_], g_v_lo[(size_t)M_ * C_];
__device__ bf16 g_y_hi[(size_t)M_ * C_], g_y_lo[(size_t)M_ * C_];   // [B,T,C]

// ---------------------------------------------------------------------------
// Helpers (baseline PTX only: mma.sync / ldmatrix / cp.async)
// ---------------------------------------------------------------------------
__device__ __forceinline__ uint32_t sptr(const void* p) {
    return (uint32_t)__cvta_generic_to_shared(p);
}
__device__ __forceinline__ void cpa16(uint32_t s, const void* g) {
    asm volatile("cp.async.cg.shared.global [%0], [%1], 16;" :: "r"(s), "l"(g));
}
#define CP_COMMIT() asm volatile("cp.async.commit_group;" ::: "memory")
#define CP_WAIT0()  asm volatile("cp.async.wait_group 0;" ::: "memory")
#define CP_WAIT1()  asm volatile("cp.async.wait_group 1;" ::: "memory")

__device__ __forceinline__ void ldsm4(uint32_t* d, uint32_t a) {
    asm volatile("ldmatrix.sync.aligned.m8n8.x4.shared.b16 {%0,%1,%2,%3}, [%4];"
                 : "=r"(d[0]), "=r"(d[1]), "=r"(d[2]), "=r"(d[3]) : "r"(a));
}
__device__ __forceinline__ void ldsm4t(uint32_t* d, uint32_t a) {
    asm volatile("ldmatrix.sync.aligned.m8n8.x4.trans.shared.b16 {%0,%1,%2,%3}, [%4];"
                 : "=r"(d[0]), "=r"(d[1]), "=r"(d[2]), "=r"(d[3]) : "r"(a));
}
__device__ __forceinline__ void mma16816(float* c, const uint32_t* a,
                                         uint32_t b0, uint32_t b1) {
    asm volatile(
        "mma.sync.aligned.m16n8k16.row.col.f32.bf16.bf16.f32 "
        "{%0,%1,%2,%3}, {%4,%5,%6,%7}, {%8,%9}, {%0,%1,%2,%3};"
        : "+f"(c[0]), "+f"(c[1]), "+f"(c[2]), "+f"(c[3])
        : "r"(a[0]), "r"(a[1]), "r"(a[2]), "r"(a[3]), "r"(b0), "r"(b1));
}
__device__ __forceinline__ void split2(float x, float y, uint32_t& hi, uint32_t& lo) {
    bf16 hx = __float2bfloat16(x), hy = __float2bfloat16(y);
    float rx = x - __bfloat162float(hx);
    float ry = y - __bfloat162float(hy);
    __nv_bfloat162 h; h.x = hx; h.y = hy;
    __nv_bfloat162 l; l.x = __float2bfloat16(rx); l.y = __float2bfloat16(ry);
    hi = *reinterpret_cast<uint32_t*>(&h);
    lo = *reinterpret_cast<uint32_t*>(&l);
}

// ---------------------------------------------------------------------------
// Split fp32 -> (hi, lo) bf16 pair, elementwise
// ---------------------------------------------------------------------------
__global__ void split_f32(const float* __restrict__ src, bf16* __restrict__ hi,
                          bf16* __restrict__ lo, int n4)
{
    for (int i = blockIdx.x * blockDim.x + threadIdx.x; i < n4;
         i += gridDim.x * blockDim.x) {
        float4 v = ((const float4*)src)[i];
        uint32_t h0, l0, h1, l1;
        split2(v.x, v.y, h0, l0);
        split2(v.z, v.w, h1, l1);
        ((uint32_t*)hi)[2 * i] = h0; ((uint32_t*)hi)[2 * i + 1] = h1;
        ((uint32_t*)lo)[2 * i] = l0; ((uint32_t*)lo)[2 * i + 1] = l1;
    }
}

// ---------------------------------------------------------------------------
// GEMM: C[M,N] = A[M,K] @ W[N,K]^T + bias, split-bf16 (3 mma passes)
// 128x128 tile, 8 warps (2x4), warp 64x32, k-step 32, 2-stage cp.async.
// MODE 1: A=x -> scatter q/k/v split-bf16 (+bias, q*0.125)
// MODE 0: A=y -> fp32 out + bias
// ---------------------------------------------------------------------------
#define GPAD    40                         // smem row elems (80 B/row)
#define GTILEB  (128 * GPAD * 2)           // 10240 B per tile
#define GSTAGEB (4 * GTILEB)               // Ahi Alo Bhi Blo
#define GSMEM   (2 * GSTAGEB)              // 81920 B

template <int MODE>
__global__ __launch_bounds__(256) void gemm_mma(
    const float* __restrict__ bias, float* __restrict__ out)
{
    constexpr int N = MODE ? 3 * C_ : C_;
    const bf16* Ahi = MODE ? g_x_hi : g_y_hi;
    const bf16* Alo = MODE ? g_x_lo : g_y_lo;
    const bf16* Bhi = MODE ? g_wa_hi : g_wp_hi;
    const bf16* Blo = MODE ? g_wa_lo : g_wp_lo;

    extern __shared__ char sm[];
    const int tid = threadIdx.x, wid = tid >> 5, lane = tid & 31;
    const int wm = wid >> 2, wn = wid & 3;
    const int m0 = blockIdx.y * 128, n0 = blockIdx.x * 128;

    float acc[4][4][4];
#pragma unroll
    for (int i = 0; i < 4; i++)
#pragma unroll
        for (int j = 0; j < 4; j++)
#pragma unroll
            for (int k = 0; k < 4; k++) acc[i][j][k] = 0.f;

    const int lr = tid >> 2;          // row loaded (0..63, x2)
    const int lc = tid & 3;           // 16B chunk in row

    auto load_stage = [&](int st, int k0) {
        char* base = sm + st * GSTAGEB;
        const bf16* srcs[4] = { Ahi, Alo, Bhi, Blo };
#pragma unroll
        for (int t4 = 0; t4 < 4; t4++) {
            const int row0 = (t4 < 2) ? m0 : n0;
#pragma unroll
            for (int i = 0; i < 2; i++) {
                const int r = lr + i * 64;
                cpa16(sptr(base + t4 * GTILEB + r * 80 + lc * 16),
                      srcs[t4] + (size_t)(row0 + r) * KD_ + k0 + lc * 8);
            }
        }
    };

    load_stage(0, 0);
    CP_COMMIT();

    const int NSTEP = KD_ / 32;
    for (int kc = 0; kc < NSTEP; kc++) {
        if (kc + 1 < NSTEP) { load_stage((kc + 1) & 1, (kc + 1) * 32); CP_COMMIT(); CP_WAIT1(); }
        else                { CP_WAIT0(); }
        __syncthreads();

        char* Ab = sm + (kc & 1) * GSTAGEB;
        char* Al = Ab + GTILEB;
        char* Bb = Ab + 2 * GTILEB;
        char* Bl = Ab + 3 * GTILEB;

#pragma unroll
        for (int kk = 0; kk < 2; kk++) {
            uint32_t ah[4][4], al[4][4];
#pragma unroll
            for (int mi = 0; mi < 4; mi++) {
                const uint32_t off = (uint32_t)((wm * 64 + mi * 16 + (lane & 15)) * 80
                                                + (kk * 16 + (lane >> 4) * 8) * 2);
                ldsm4(ah[mi], sptr(Ab + off));
                ldsm4(al[mi], sptr(Al + off));
            }
#pragma unroll
            for (int np = 0; np < 2; np++) {
                uint32_t bh[4], bl[4];
                const uint32_t boff = (uint32_t)(
                    (wn * 32 + np * 16 + (lane & 7) + ((lane >> 4) << 3)) * 80
                    + (kk * 16 + ((lane >> 3) & 1) * 8) * 2);
                ldsm4(bh, sptr(Bb + boff));
                ldsm4(bl, sptr(Bl + boff));
#pragma unroll
                for (int mi = 0; mi < 4; mi++) {
                    mma16816(acc[mi][2 * np],     ah[mi], bh[0], bh[1]);
                    mma16816(acc[mi][2 * np + 1], ah[mi], bh[2], bh[3]);
                    mma16816(acc[mi][2 * np],     ah[mi], bl[0], bl[1]);
                    mma16816(acc[mi][2 * np + 1], ah[mi], bl[2], bl[3]);
                    mma16816(acc[mi][2 * np],     al[mi], bh[0], bh[1]);
                    mma16816(acc[mi][2 * np + 1], al[mi], bh[2], bh[3]);
                }
            }
        }
        __syncthreads();
    }

    // epilogue
#pragma unroll
    for (int mi = 0; mi < 4; mi++) {
        const int m = m0 + wm * 64 + mi * 16 + (lane >> 2);
#pragma unroll
        for (int ni = 0; ni < 4; ni++) {
            const int n = n0 + wn * 32 + ni * 8 + (lane & 3) * 2;
            const float b0 = bias[n], b1 = bias[n + 1];
            float v00 = acc[mi][ni][0] + b0, v01 = acc[mi][ni][1] + b1;  // row m
            float v10 = acc[mi][ni][2] + b0, v11 = acc[mi][ni][3] + b1;  // row m+8
            if (MODE == 0) {
                *(float2*)(out + (size_t)m * C_ + n)       = make_float2(v00, v01);
                *(float2*)(out + (size_t)(m + 8) * C_ + n) = make_float2(v10, v11);
            } else {
                const int sec = n >> 10;
                const int cc = n & 1023, h = cc >> 6, d = cc & 63;
                const int bb = m >> 11, t = m & 2047;
                if (sec == 0) { v00 *= 0.125f; v01 *= 0.125f; v10 *= 0.125f; v11 *= 0.125f; }
                bf16* dh = (sec == 0) ? g_q_hi : (sec == 1) ? g_k_hi : g_v_hi;
                bf16* dl = (sec == 0) ? g_q_lo : (sec == 1) ? g_k_lo : g_v_lo;
                const size_t base0 = ((size_t)((bb * H_ + h) * T_) + t) * DK_ + d;
                uint32_t h0, l0, h1, l1;
                split2(v00, v01, h0, l0);
                split2(v10, v11, h1, l1);
                *(uint32_t*)(dh + base0)            = h0;
                *(uint32_t*)(dl + base0)            = l0;
                *(uint32_t*)(dh + base0 + 8 * DK_)  = h1;
                *(uint32_t*)(dl + base0 + 8 * DK_)  = l1;
            }
        }
    }
}

// ---------------------------------------------------------------------------
// Flash attention, split-bf16 mma. CTA: 128 queries x 1 head, 8 warps
// (16 q-rows each). Key tiles of 128, fp32 online softmax in C-fragments.
// ---------------------------------------------------------------------------
#define ASTRIDE 144                         // 72 elems/row
#define ATILEB  (128 * ASTRIDE)             // 18432 B
#define A_QH 0
#define A_QL (1 * ATILEB)
#define A_KH (2 * ATILEB)
#define A_KL (3 * ATILEB)
#define A_VH (4 * ATILEB)
#define A_VL (5 * ATILEB)
#define ASMEM (6 * ATILEB)                  // 110592 B

__global__ __launch_bounds__(256) void attn_mma()
{
    extern __shared__ char sm[];
    const int tid = threadIdx.x, wid = tid >> 5, lane = tid & 31;
    const int bh = blockIdx.x;
    const int q0 = blockIdx.y * 128;
    const size_t hb = (size_t)bh * T_ * DK_;

    // load Q hi/lo (1024 16B-chunks per tensor)
#pragma unroll
    for (int i = 0; i < 4; i++) {
        const int id = tid + i * 256;
        const int r = id >> 3, c = id & 7;
        const size_t g = hb + (size_t)(q0 + r) * DK_ + c * 8;
        cpa16(sptr(sm + A_QH + r * ASTRIDE + c * 16), g_q_hi + g);
        cpa16(sptr(sm + A_QL + r * ASTRIDE + c * 16), g_q_lo + g);
    }
    CP_COMMIT();

    float o[8][4];
#pragma unroll
    for (int i = 0; i < 8; i++)
#pragma unroll
        for (int j = 0; j < 4; j++) o[i][j] = 0.f;
    float mrow0 = -1e30f, mrow1 = -1e30f, lrow0 = 0.f, lrow1 = 0.f;

    for (int kt = 0; kt < T_ / 128; kt++) {
        // load K/V hi/lo tile
#pragma unroll
        for (int i = 0; i < 4; i++) {
            const int id = tid + i * 256;
            const int r = id >> 3, c = id & 7;
            const size_t g = hb + (size_t)(kt * 128 + r) * DK_ + c * 8;
            const uint32_t so = r * ASTRIDE + c * 16;
            cpa16(sptr(sm + A_KH + so), g_k_hi + g);
            cpa16(sptr(sm + A_KL + so), g_k_lo + g);
            cpa16(sptr(sm + A_VH + so), g_v_hi + g);
            cpa16(sptr(sm + A_VL + so), g_v_lo + g);
        }
        CP_COMMIT();
        CP_WAIT0();
        __syncthreads();

        // S = Q K^T (split, fp32 accum): s[16 n-tiles][4]
        float s[16][4];
#pragma unroll
        for (int i = 0; i < 16; i++)
#pragma unroll
            for (int j = 0; j < 4; j++) s[i][j] = 0.f;

#pragma unroll
        for (int kk = 0; kk < 4; kk++) {
            uint32_t qh[4], ql[4];
            const uint32_t qoff = (uint32_t)((wid * 16 + (lane & 15)) * ASTRIDE
                                             + (kk * 16 + (lane >> 4) * 8) * 2);
            ldsm4(qh, sptr(sm + A_QH + qoff));
            ldsm4(ql, sptr(sm + A_QL + qoff));
#pragma unroll
            for (int np = 0; np < 8; np++) {
                uint32_t kh[4], kl[4];
                const uint32_t koff = (uint32_t)(
                    (np * 16 + (lane & 7) + ((lane >> 4) << 3)) * ASTRIDE
                    + (kk * 16 + ((lane >> 3) & 1) * 8) * 2);
                ldsm4(kh, sptr(sm + A_KH + koff));
                ldsm4(kl, sptr(sm + A_KL + koff));
                mma16816(s[2 * np],     qh, kh[0], kh[1]);
                mma16816(s[2 * np + 1], qh, kh[2], kh[3]);
                mma16816(s[2 * np],     qh, kl[0], kl[1]);
                mma16816(s[2 * np + 1], qh, kl[2], kl[3]);
                mma16816(s[2 * np],     ql, kh[0], kh[1]);
                mma16816(s[2 * np + 1], ql, kh[2], kh[3]);
            }
        }

        // online softmax (rows: lane>>2 and +8; quad shuffles over lane&3)
        float mx0 = -1e30f, mx1 = -1e30f;
#pragma unroll
        for (int nt = 0; nt < 16; nt++) {
            mx0 = fmaxf(mx0, fmaxf(s[nt][0], s[nt][1]));
            mx1 = fmaxf(mx1, fmaxf(s[nt][2], s[nt][3]));
        }
        mx0 = fmaxf(mx0, __shfl_xor_sync(0xffffffffu, mx0, 1));
        mx0 = fmaxf(mx0, __shfl_xor_sync(0xffffffffu, mx0, 2));
        mx1 = fmaxf(mx1, __shfl_xor_sync(0xffffffffu, mx1, 1));
        mx1 = fmaxf(mx1, __shfl_xor_sync(0xffffffffu, mx1, 2));
        const float mn0 = fmaxf(mrow0, mx0), mn1 = fmaxf(mrow1, mx1);
        const float cor0 = __expf(mrow0 - mn0), cor1 = __expf(mrow1 - mn1);
        mrow0 = mn0; mrow1 = mn1;
        float sum0 = 0.f, sum1 = 0.f;
#pragma unroll
        for (int nt = 0; nt < 16; nt++) {
            s[nt][0] = __expf(s[nt][0] - mn0); sum0 += s[nt][0];
            s[nt][1] = __expf(s[nt][1] - mn0); sum0 += s[nt][1];
            s[nt][2] = __expf(s[nt][2] - mn1); sum1 += s[nt][2];
            s[nt][3] = __expf(s[nt][3] - mn1); sum1 += s[nt][3];
        }
        sum0 += __shfl_xor_sync(0xffffffffu, sum0, 1);
        sum0 += __shfl_xor_sync(0xffffffffu, sum0, 2);
        sum1 += __shfl_xor_sync(0xffffffffu, sum1, 1);
        sum1 += __shfl_xor_sync(0xffffffffu, sum1, 2);
        lrow0 = lrow0 * cor0 + sum0;
        lrow1 = lrow1 * cor1 + sum1;
#pragma unroll
        for (int nt2 = 0; nt2 < 8; nt2++) {
            o[nt2][0] *= cor0; o[nt2][1] *= cor0;
            o[nt2][2] *= cor1; o[nt2][3] *= cor1;
        }

        // O += P V (split P from S accum fragments; V via trans ldmatrix)
#pragma unroll
        for (int j = 0; j < 8; j++) {
            uint32_t ph[4], pl[4];
            split2(s[2 * j][0],     s[2 * j][1],     ph[0], pl[0]);
            split2(s[2 * j][2],     s[2 * j][3],     ph[1], pl[1]);
            split2(s[2 * j + 1][0], s[2 * j + 1][1], ph[2], pl[2]);
            split2(s[2 * j + 1][2], s[2 * j + 1][3], ph[3], pl[3]);
#pragma unroll
            for (int np = 0; np < 4; np++) {
                uint32_t vh[4], vl[4];
                const uint32_t voff = (uint32_t)(
                    (j * 16 + (lane & 15)) * ASTRIDE
                    + (np * 16 + (lane >> 4) * 8) * 2);
                ldsm4t(vh, sptr(sm + A_VH + voff));
                ldsm4t(vl, sptr(sm + A_VL + voff));
                mma16816(o[2 * np],     ph, vh[0], vh[1]);
                mma16816(o[2 * np + 1], ph, vh[2], vh[3]);
                mma16816(o[2 * np],     ph, vl[0], vl[1]);
                mma16816(o[2 * np + 1], ph, vl[2], vl[3]);
                mma16816(o[2 * np],     pl, vh[0], vh[1]);
                mma16816(o[2 * np + 1], pl, vh[2], vh[3]);
            }
        }
        __syncthreads();
    }

    // epilogue: normalize, split to bf16 hi/lo, write y [B,T,C]
    const float inv0 = 1.f / lrow0, inv1 = 1.f / lrow1;
    const int bb = bh >> 4, h = bh & 15;
    const int r0 = q0 + wid * 16 + (lane >> 2);
#pragma unroll
    for (int nt2 = 0; nt2 < 8; nt2++) {
        const int col = h * DK_ + nt2 * 8 + (lane & 3) * 2;
        const size_t i0 = (size_t)(bb * T_ + r0) * C_ + col;
        const size_t i1 = (size_t)(bb * T_ + r0 + 8) * C_ + col;
        uint32_t h0, l0, h1, l1;
        split2(o[nt2][0] * inv0, o[nt2][1] * inv0, h0, l0);
        split2(o[nt2][2] * inv1, o[nt2][3] * inv1, h1, l1);
        *(uint32_t*)(g_y_hi + i0) = h0;  *(uint32_t*)(g_y_lo + i0) = l0;
        *(uint32_t*)(g_y_hi + i1) = h1;  *(uint32_t*)(g_y_lo + i1) = l1;
    }
}

// ---------------------------------------------------------------------------
extern "C" void kernel_launch(void* const* d_in, const int* in_sizes, int n_in,
                              void* d_out, int out_size)
{
    const float* x      = (const float*)d_in[0];
    const float* w_attn = (const float*)d_in[1];
    const float* b_attn = (const float*)d_in[2];
    const float* w_proj = (const float*)d_in[3];
    const float* b_proj = (const float*)d_in[4];
    float* out = (float*)d_out;

    static bool inited = false;
    if (!inited) {
        cudaFuncSetAttribute(gemm_mma<1>, cudaFuncAttributeMaxDynamicSharedMemorySize, GSMEM);
        cudaFuncSetAttribute(gemm_mma<0>, cudaFuncAttributeMaxDynamicSharedMemorySize, GSMEM);
        cudaFuncSetAttribute(attn_mma,    cudaFuncAttributeMaxDynamicSharedMemorySize, ASMEM);
        inited = true;
    }

    bf16 *xh, *xl, *wah, *wal, *wph, *wpl;
    cudaGetSymbolAddress((void**)&xh,  g_x_hi);  cudaGetSymbolAddress((void**)&xl,  g_x_lo);
    cudaGetSymbolAddress((void**)&wah, g_wa_hi); cudaGetSymbolAddress((void**)&wal, g_wa_lo);
    cudaGetSymbolAddress((void**)&wph, g_wp_hi); cudaGetSymbolAddress((void**)&wpl, g_wp_lo);

    // 0) split fp32 -> hi/lo bf16
    split_f32<<<4096, 256>>>(x,      xh,  xl,  (M_ * C_) / 4);
    split_f32<<<1536, 256>>>(w_attn, wah, wal, (3 * C_ * C_) / 4);
    split_f32<<<512,  256>>>(w_proj, wph, wpl, (C_ * C_) / 4);

    // 1) QKV projection -> split q/k/v [B,H,T,dk]
    gemm_mma<1><<<dim3((3 * C_) / 128, M_ / 128), 256, GSMEM>>>(b_attn, nullptr);

    // 2) flash attention -> split y [B,T,C]
    attn_mma<<<dim3(B_ * H_, T_ / 128), 256, ASMEM>>>();

    // 3) output projection -> out
    gemm_mma<0><<<dim3(C_ / 128, M_ / 128), 256, GSMEM>>>(b_proj, out);
}

// round 4
// speedup vs baseline: 5.4358x; 1.5564x over previous
#include <cuda_runtime.h>
#include <cuda_fp16.h>
#include <cstdint>

#define B_  4
#define T_  2048
#define C_  1024
#define H_  16
#define DK_ 64
#define M_  (B_ * T_)      // 8192
#define KD_ 1024

// ---------------------------------------------------------------------------
// Scratch (static __device__ arrays)
// ---------------------------------------------------------------------------
__device__ __half g_xh[(size_t)M_ * C_], g_xl[(size_t)M_ * C_];
__device__ __half g_wa[(size_t)3 * C_ * C_];
__device__ __half g_wp[(size_t)C_ * C_];
__device__ __half g_qh[(size_t)M_ * C_], g_ql[(size_t)M_ * C_];  // [B,H,T,dk]
__device__ __half g_k [(size_t)M_ * C_];                          // [B,H,T,dk]
__device__ __half g_v [(size_t)M_ * C_];
__device__ __half g_yh[(size_t)M_ * C_], g_yl[(size_t)M_ * C_];  // [B,T,C]

// ---------------------------------------------------------------------------
// Helpers (baseline PTX: mma.sync f16 / ldmatrix / cp.async)
// ---------------------------------------------------------------------------
__device__ __forceinline__ uint32_t sptr(const void* p) {
    return (uint32_t)__cvta_generic_to_shared(p);
}
__device__ __forceinline__ void cpa16(uint32_t s, const void* g) {
    asm volatile("cp.async.cg.shared.global [%0], [%1], 16;" :: "r"(s), "l"(g));
}
#define CP_COMMIT() asm volatile("cp.async.commit_group;" ::: "memory")
#define CP_WAIT0()  asm volatile("cp.async.wait_group 0;" ::: "memory")
#define CP_WAIT1()  asm volatile("cp.async.wait_group 1;" ::: "memory")

__device__ __forceinline__ void ldsm4(uint32_t* d, uint32_t a) {
    asm volatile("ldmatrix.sync.aligned.m8n8.x4.shared.b16 {%0,%1,%2,%3}, [%4];"
                 : "=r"(d[0]), "=r"(d[1]), "=r"(d[2]), "=r"(d[3]) : "r"(a));
}
__device__ __forceinline__ void ldsm4t(uint32_t* d, uint32_t a) {
    asm volatile("ldmatrix.sync.aligned.m8n8.x4.trans.shared.b16 {%0,%1,%2,%3}, [%4];"
                 : "=r"(d[0]), "=r"(d[1]), "=r"(d[2]), "=r"(d[3]) : "r"(a));
}
__device__ __forceinline__ void mma16816(float* c, const uint32_t* a,
                                         uint32_t b0, uint32_t b1) {
    asm volatile(
        "mma.sync.aligned.m16n8k16.row.col.f32.f16.f16.f32 "
        "{%0,%1,%2,%3}, {%4,%5,%6,%7}, {%8,%9}, {%0,%1,%2,%3};"
        : "+f"(c[0]), "+f"(c[1]), "+f"(c[2]), "+f"(c[3])
        : "r"(a[0]), "r"(a[1]), "r"(a[2]), "r"(a[3]), "r"(b0), "r"(b1));
}
__device__ __forceinline__ void split2h(float x, float y, uint32_t& hi, uint32_t& lo) {
    __half hx = __float2half_rn(x), hy = __float2half_rn(y);
    __half lx = __float2half_rn(x - __half2float(hx));
    __half ly = __float2half_rn(y - __half2float(hy));
    __half2 h = __halves2half2(hx, hy), l = __halves2half2(lx, ly);
    hi = *reinterpret_cast<uint32_t*>(&h);
    lo = *reinterpret_cast<uint32_t*>(&l);
}

// ---------------------------------------------------------------------------
// Preprocessing: split x -> (hi,lo) fp16; cast weights -> fp16
// ---------------------------------------------------------------------------
__global__ void split_f32h(const float* __restrict__ src, __half* __restrict__ hi,
                           __half* __restrict__ lo, int n4)
{
    for (int i = blockIdx.x * blockDim.x + threadIdx.x; i < n4;
         i += gridDim.x * blockDim.x) {
        float4 v = ((const float4*)src)[i];
        uint32_t h0, l0, h1, l1;
        split2h(v.x, v.y, h0, l0);
        split2h(v.z, v.w, h1, l1);
        ((uint32_t*)hi)[2 * i] = h0; ((uint32_t*)hi)[2 * i + 1] = h1;
        ((uint32_t*)lo)[2 * i] = l0; ((uint32_t*)lo)[2 * i + 1] = l1;
    }
}
__global__ void cast_f32h(const float* __restrict__ src, __half* __restrict__ dst, int n4)
{
    for (int i = blockIdx.x * blockDim.x + threadIdx.x; i < n4;
         i += gridDim.x * blockDim.x) {
        float4 v = ((const float4*)src)[i];
        __half2 a = __floats2half2_rn(v.x, v.y);
        __half2 b = __floats2half2_rn(v.z, v.w);
        ((uint32_t*)dst)[2 * i]     = *reinterpret_cast<uint32_t*>(&a);
        ((uint32_t*)dst)[2 * i + 1] = *reinterpret_cast<uint32_t*>(&b);
    }
}

// ---------------------------------------------------------------------------
// GEMM: C[M,N] = (Ah+Al)[M,K] @ W[N,K]^T + bias  (2 MMA passes, fp16)
// 128x128 tile, 8 warps (2x4), warp 64x32, k-step 32, 2-stage cp.async.
// MODE 1: A=x  -> scatter q(split,*0.125)/k/v fp16 in [B,H,T,dk]
// MODE 0: A=y  -> fp32 out + bias
// ---------------------------------------------------------------------------
#define GROWB   80                          // 32 fp16 + pad
#define GTILEB  (128 * GROWB)               // 10240 B
#define GSTAGEB (3 * GTILEB)                // Ah Al B
#define GSMEM   (2 * GSTAGEB)               // 61440 B

template <int MODE>
__global__ __launch_bounds__(256, 2) void gemm_mma(
    const float* __restrict__ bias, float* __restrict__ out)
{
    const __half* Ah = MODE ? g_xh : g_yh;
    const __half* Al = MODE ? g_xl : g_yl;
    const __half* Bs = MODE ? g_wa : g_wp;

    extern __shared__ char sm[];
    const int tid = threadIdx.x, wid = tid >> 5, lane = tid & 31;
    const int wm = wid >> 2, wn = wid & 3;
    const int m0 = blockIdx.y * 128, n0 = blockIdx.x * 128;

    float acc[4][4][4];
#pragma unroll
    for (int i = 0; i < 4; i++)
#pragma unroll
        for (int j = 0; j < 4; j++)
#pragma unroll
            for (int k = 0; k < 4; k++) acc[i][j][k] = 0.f;

    auto load_stage = [&](int st, int k0) {
        char* base = sm + st * GSTAGEB;
        const __half* srcs[3] = { Ah, Al, Bs };
#pragma unroll
        for (int t = 0; t < 3; t++) {
            const int row0 = (t < 2) ? m0 : n0;
#pragma unroll
            for (int i = 0; i < 2; i++) {
                const int id = tid + i * 256;        // 0..511
                const int r = id >> 2, c4 = id & 3;  // row, 16B chunk
                cpa16(sptr(base + t * GTILEB + r * GROWB + c4 * 16),
                      srcs[t] + (size_t)(row0 + r) * KD_ + k0 + c4 * 8);
            }
        }
    };

    load_stage(0, 0);
    CP_COMMIT();

    const int NSTEP = KD_ / 32;
    for (int kc = 0; kc < NSTEP; kc++) {
        if (kc + 1 < NSTEP) { load_stage((kc + 1) & 1, (kc + 1) * 32); CP_COMMIT(); CP_WAIT1(); }
        else                { CP_WAIT0(); }
        __syncthreads();

        char* Abh = sm + (kc & 1) * GSTAGEB;
        char* Abl = Abh + GTILEB;
        char* Bb  = Abh + 2 * GTILEB;

#pragma unroll
        for (int kk = 0; kk < 2; kk++) {
            uint32_t ah[4][4], al[4][4];
#pragma unroll
            for (int mi = 0; mi < 4; mi++) {
                const uint32_t off = (uint32_t)((wm * 64 + mi * 16 + (lane & 15)) * GROWB
                                                + (kk * 16 + (lane >> 4) * 8) * 2);
                ldsm4(ah[mi], sptr(Abh + off));
                ldsm4(al[mi], sptr(Abl + off));
            }
#pragma unroll
            for (int np = 0; np < 2; np++) {
                uint32_t bh[4];
                const uint32_t boff = (uint32_t)(
                    (wn * 32 + np * 16 + (lane & 7) + ((lane >> 4) << 3)) * GROWB
                    + (kk * 16 + ((lane >> 3) & 1) * 8) * 2);
                ldsm4(bh, sptr(Bb + boff));
                // pass 1 (hi): 8 independent accumulator targets
#pragma unroll
                for (int mi = 0; mi < 4; mi++) {
                    mma16816(acc[mi][2 * np],     ah[mi], bh[0], bh[1]);
                    mma16816(acc[mi][2 * np + 1], ah[mi], bh[2], bh[3]);
                }
                // pass 2 (lo): same targets, distance 8
#pragma unroll
                for (int mi = 0; mi < 4; mi++) {
                    mma16816(acc[mi][2 * np],     al[mi], bh[0], bh[1]);
                    mma16816(acc[mi][2 * np + 1], al[mi], bh[2], bh[3]);
                }
            }
        }
        __syncthreads();
    }

    // epilogue
#pragma unroll
    for (int mi = 0; mi < 4; mi++) {
        const int m = m0 + wm * 64 + mi * 16 + (lane >> 2);
#pragma unroll
        for (int ni = 0; ni < 4; ni++) {
            const int n = n0 + wn * 32 + ni * 8 + (lane & 3) * 2;
            const float b0 = bias[n], b1 = bias[n + 1];
            float v00 = acc[mi][ni][0] + b0, v01 = acc[mi][ni][1] + b1;  // row m
            float v10 = acc[mi][ni][2] + b0, v11 = acc[mi][ni][3] + b1;  // row m+8
            if (MODE == 0) {
                *(float2*)(out + (size_t)m * C_ + n)       = make_float2(v00, v01);
                *(float2*)(out + (size_t)(m + 8) * C_ + n) = make_float2(v10, v11);
            } else {
                const int sec = n >> 10;
                const int cc = n & 1023, h = cc >> 6, d = cc & 63;
                const int bb = m >> 11, t = m & 2047;
                const size_t base0 = ((size_t)((bb * H_ + h) * T_) + t) * DK_ + d;
                if (sec == 0) {
                    v00 *= 0.125f; v01 *= 0.125f; v10 *= 0.125f; v11 *= 0.125f;
                    uint32_t h0, l0, h1, l1;
                    split2h(v00, v01, h0, l0);
                    split2h(v10, v11, h1, l1);
                    *(uint32_t*)(g_qh + base0)           = h0;
                    *(uint32_t*)(g_ql + base0)           = l0;
                    *(uint32_t*)(g_qh + base0 + 8 * DK_) = h1;
                    *(uint32_t*)(g_ql + base0 + 8 * DK_) = l1;
                } else {
                    __half* dst = (sec == 1) ? g_k : g_v;
                    __half2 p0 = __floats2half2_rn(v00, v01);
                    __half2 p1 = __floats2half2_rn(v10, v11);
                    *(uint32_t*)(dst + base0)           = *reinterpret_cast<uint32_t*>(&p0);
                    *(uint32_t*)(dst + base0 + 8 * DK_) = *reinterpret_cast<uint32_t*>(&p1);
                }
            }
        }
    }
}

// ---------------------------------------------------------------------------
// Flash attention (fp16 2-pass). CTA: 128 queries x 1 head, 8 warps.
// Q (split) preloaded to registers; K/V single fp16, double-buffered cp.async.
// ---------------------------------------------------------------------------
#define AROWB   144                          // 64 fp16 + pad
#define ATILEB  (128 * AROWB)                // 18432 B
#define ASTAGEB (2 * ATILEB)                 // K + V
#define ASMEM   (2 * ASTAGEB)                // 73728 B

__global__ __launch_bounds__(256) void attn_mma()
{
    extern __shared__ char sm[];
    const int tid = threadIdx.x, wid = tid >> 5, lane = tid & 31;
    const int bh = blockIdx.x;
    const int q0 = blockIdx.y * 128;
    const size_t hb = (size_t)bh * T_ * DK_;

    // ---- stage Q (hi into stage0-K area, lo into stage0-V area) ----
#pragma unroll
    for (int i = 0; i < 4; i++) {
        const int id = tid + i * 256;
        const int r = id >> 3, c = id & 7;
        const size_t g = hb + (size_t)(q0 + r) * DK_ + c * 8;
        const uint32_t so = r * AROWB + c * 16;
        cpa16(sptr(sm + so),          g_qh + g);
        cpa16(sptr(sm + ATILEB + so), g_ql + g);
    }
    CP_COMMIT();
    CP_WAIT0();
    __syncthreads();

    uint32_t qh[4][4], ql[4][4];
#pragma unroll
    for (int kk = 0; kk < 4; kk++) {
        const uint32_t qoff = (uint32_t)((wid * 16 + (lane & 15)) * AROWB
                                         + (kk * 16 + (lane >> 4) * 8) * 2);
        ldsm4(qh[kk], sptr(sm + qoff));
        ldsm4(ql[kk], sptr(sm + ATILEB + qoff));
    }
    __syncthreads();

    // ---- K/V pipeline ----
    auto load_kv = [&](int st, int kt) {
        char* base = sm + st * ASTAGEB;
#pragma unroll
        for (int i = 0; i < 4; i++) {
            const int id = tid + i * 256;
            const int r = id >> 3, c = id & 7;
            const size_t g = hb + (size_t)(kt * 128 + r) * DK_ + c * 8;
            const uint32_t so = r * AROWB + c * 16;
            cpa16(sptr(base + so),          g_k + g);
            cpa16(sptr(base + ATILEB + so), g_v + g);
        }
    };

    load_kv(0, 0); CP_COMMIT();
    load_kv(1, 1); CP_COMMIT();

    float o[8][4];
#pragma unroll
    for (int i = 0; i < 8; i++)
#pragma unroll
        for (int j = 0; j < 4; j++) o[i][j] = 0.f;
    float mrow0 = -1e30f, mrow1 = -1e30f, lrow0 = 0.f, lrow1 = 0.f;

    const int NT = T_ / 128;
    for (int kt = 0; kt < NT; kt++) {
        if (kt + 1 < NT) CP_WAIT1(); else CP_WAIT0();
        __syncthreads();
        char* Kb = sm + (kt & 1) * ASTAGEB;
        char* Vb = Kb + ATILEB;

        // S = (qh+ql) K^T
        float s[16][4];
#pragma unroll
        for (int i = 0; i < 16; i++)
#pragma unroll
            for (int j = 0; j < 4; j++) s[i][j] = 0.f;

#pragma unroll
        for (int kk = 0; kk < 4; kk++) {
#pragma unroll
            for (int np = 0; np < 8; np++) {
                uint32_t kh[4];
                const uint32_t koff = (uint32_t)(
                    (np * 16 + (lane & 7) + ((lane >> 4) << 3)) * AROWB
                    + (kk * 16 + ((lane >> 3) & 1) * 8) * 2);
                ldsm4(kh, sptr(Kb + koff));
                mma16816(s[2 * np],     qh[kk], kh[0], kh[1]);
                mma16816(s[2 * np + 1], qh[kk], kh[2], kh[3]);
                mma16816(s[2 * np],     ql[kk], kh[0], kh[1]);
                mma16816(s[2 * np + 1], ql[kk], kh[2], kh[3]);
            }
        }

        // online softmax (rows lane>>2 and +8)
        float mx0 = -1e30f, mx1 = -1e30f;
#pragma unroll
        for (int nt = 0; nt < 16; nt++) {
            mx0 = fmaxf(mx0, fmaxf(s[nt][0], s[nt][1]));
            mx1 = fmaxf(mx1, fmaxf(s[nt][2], s[nt][3]));
        }
        mx0 = fmaxf(mx0, __shfl_xor_sync(0xffffffffu, mx0, 1));
        mx0 = fmaxf(mx0, __shfl_xor_sync(0xffffffffu, mx0, 2));
        mx1 = fmaxf(mx1, __shfl_xor_sync(0xffffffffu, mx1, 1));
        mx1 = fmaxf(mx1, __shfl_xor_sync(0xffffffffu, mx1, 2));
        const float mn0 = fmaxf(mrow0, mx0), mn1 = fmaxf(mrow1, mx1);
        const float cor0 = __expf(mrow0 - mn0), cor1 = __expf(mrow1 - mn1);
        mrow0 = mn0; mrow1 = mn1;
        float sum0 = 0.f, sum1 = 0.f;
#pragma unroll
        for (int nt = 0; nt < 16; nt++) {
            s[nt][0] = __expf(s[nt][0] - mn0); sum0 += s[nt][0];
            s[nt][1] = __expf(s[nt][1] - mn0); sum0 += s[nt][1];
            s[nt][2] = __expf(s[nt][2] - mn1); sum1 += s[nt][2];
            s[nt][3] = __expf(s[nt][3] - mn1); sum1 += s[nt][3];
        }
        sum0 += __shfl_xor_sync(0xffffffffu, sum0, 1);
        sum0 += __shfl_xor_sync(0xffffffffu, sum0, 2);
        sum1 += __shfl_xor_sync(0xffffffffu, sum1, 1);
        sum1 += __shfl_xor_sync(0xffffffffu, sum1, 2);
        lrow0 = lrow0 * cor0 + sum0;
        lrow1 = lrow1 * cor1 + sum1;
#pragma unroll
        for (int nt2 = 0; nt2 < 8; nt2++) {
            o[nt2][0] *= cor0; o[nt2][1] *= cor0;
            o[nt2][2] *= cor1; o[nt2][3] *= cor1;
        }

        // O += (Ph+Pl) V
#pragma unroll
        for (int j = 0; j < 8; j++) {
            uint32_t ph[4], pl[4];
            split2h(s[2 * j][0],     s[2 * j][1],     ph[0], pl[0]);
            split2h(s[2 * j][2],     s[2 * j][3],     ph[1], pl[1]);
            split2h(s[2 * j + 1][0], s[2 * j + 1][1], ph[2], pl[2]);
            split2h(s[2 * j + 1][2], s[2 * j + 1][3], ph[3], pl[3]);
#pragma unroll
            for (int np = 0; np < 4; np++) {
                uint32_t vh[4];
                const uint32_t voff = (uint32_t)(
                    (j * 16 + (lane & 15)) * AROWB
                    + (np * 16 + (lane >> 4) * 8) * 2);
                ldsm4t(vh, sptr(Vb + voff));
                mma16816(o[2 * np],     ph, vh[0], vh[1]);
                mma16816(o[2 * np + 1], ph, vh[2], vh[3]);
                mma16816(o[2 * np],     pl, vh[0], vh[1]);
                mma16816(o[2 * np + 1], pl, vh[2], vh[3]);
            }
        }
        __syncthreads();
        if (kt + 2 < NT) { load_kv(kt & 1, kt + 2); CP_COMMIT(); }
    }

    // epilogue: normalize, split fp16, write y [B,T,C]
    const float inv0 = 1.f / lrow0, inv1 = 1.f / lrow1;
    const int bb = bh >> 4, h = bh & 15;
    const int r0 = q0 + wid * 16 + (lane >> 2);
#pragma unroll
    for (int nt2 = 0; nt2 < 8; nt2++) {
        const int col = h * DK_ + nt2 * 8 + (lane & 3) * 2;
        const size_t i0 = (size_t)(bb * T_ + r0) * C_ + col;
        const size_t i1 = (size_t)(bb * T_ + r0 + 8) * C_ + col;
        uint32_t h0, l0, h1, l1;
        split2h(o[nt2][0] * inv0, o[nt2][1] * inv0, h0, l0);
        split2h(o[nt2][2] * inv1, o[nt2][3] * inv1, h1, l1);
        *(uint32_t*)(g_yh + i0) = h0;  *(uint32_t*)(g_yl + i0) = l0;
        *(uint32_t*)(g_yh + i1) = h1;  *(uint32_t*)(g_yl + i1) = l1;
    }
}

// ---------------------------------------------------------------------------
extern "C" void kernel_launch(void* const* d_in, const int* in_sizes, int n_in,
                              void* d_out, int out_size)
{
    const float* x      = (const float*)d_in[0];
    const float* w_attn = (const float*)d_in[1];
    const float* b_attn = (const float*)d_in[2];
    const float* w_proj = (const float*)d_in[3];
    const float* b_proj = (const float*)d_in[4];
    float* out = (float*)d_out;

    static bool inited = false;
    if (!inited) {
        cudaFuncSetAttribute(gemm_mma<1>, cudaFuncAttributeMaxDynamicSharedMemorySize, GSMEM);
        cudaFuncSetAttribute(gemm_mma<0>, cudaFuncAttributeMaxDynamicSharedMemorySize, GSMEM);
        cudaFuncSetAttribute(attn_mma,    cudaFuncAttributeMaxDynamicSharedMemorySize, ASMEM);
        inited = true;
    }

    __half *xh, *xl, *wa, *wp;
    cudaGetSymbolAddress((void**)&xh, g_xh); cudaGetSymbolAddress((void**)&xl, g_xl);
    cudaGetSymbolAddress((void**)&wa, g_wa); cudaGetSymbolAddress((void**)&wp, g_wp);

    // 0) preprocessing
    split_f32h<<<4096, 256>>>(x, xh, xl, (M_ * C_) / 4);
    cast_f32h<<<1536, 256>>>(w_attn, wa, (3 * C_ * C_) / 4);
    cast_f32h<<<512,  256>>>(w_proj, wp, (C_ * C_) / 4);

    // 1) QKV projection -> q(split)/k/v fp16 [B,H,T,dk]
    gemm_mma<1><<<dim3((3 * C_) / 128, M_ / 128), 256, GSMEM>>>(b_attn, nullptr);

    // 2) flash attention -> y(split) [B,T,C]
    attn_mma<<<dim3(B_ * H_, T_ / 128), 256, ASMEM>>>();

    // 3) output projection -> out (fp32)
    gemm_mma<0><<<dim3(C_ / 128, M_ / 128), 256, GSMEM>>>(b_proj, out);
}

// round 5
// speedup vs baseline: 8.4918x; 1.5622x over previous
#include <cuda_runtime.h>
#include <cuda_fp16.h>
#include <cstdint>

#define B_  4
#define T_  2048
#define C_  1024
#define H_  16
#define DK_ 64
#define M_  (B_ * T_)      // 8192
#define KD_ 1024

// ---------------------------------------------------------------------------
// Scratch (static __device__ arrays)
// ---------------------------------------------------------------------------
__device__ __half g_x [(size_t)M_ * C_];
__device__ __half g_wa[(size_t)3 * C_ * C_];
__device__ __half g_wp[(size_t)C_ * C_];
__device__ __half g_q [(size_t)M_ * C_];   // [B,H,T,dk], pre-scaled by 0.125
__device__ __half g_k [(size_t)M_ * C_];   // [B,H,T,dk]
__device__ __half g_v [(size_t)M_ * C_];
__device__ __half g_y [(size_t)M_ * C_];   // [B,T,C]

// ---------------------------------------------------------------------------
// Helpers (baseline PTX: mma.sync f16 / ldmatrix / cp.async)
// ---------------------------------------------------------------------------
__device__ __forceinline__ uint32_t sptr(const void* p) {
    return (uint32_t)__cvta_generic_to_shared(p);
}
__device__ __forceinline__ void cpa16(uint32_t s, const void* g) {
    asm volatile("cp.async.cg.shared.global [%0], [%1], 16;" :: "r"(s), "l"(g));
}
#define CP_COMMIT() asm volatile("cp.async.commit_group;" ::: "memory")
#define CP_WAIT0()  asm volatile("cp.async.wait_group 0;" ::: "memory")
#define CP_WAIT1()  asm volatile("cp.async.wait_group 1;" ::: "memory")

__device__ __forceinline__ void ldsm4(uint32_t* d, uint32_t a) {
    asm volatile("ldmatrix.sync.aligned.m8n8.x4.shared.b16 {%0,%1,%2,%3}, [%4];"
                 : "=r"(d[0]), "=r"(d[1]), "=r"(d[2]), "=r"(d[3]) : "r"(a));
}
__device__ __forceinline__ void ldsm4t(uint32_t* d, uint32_t a) {
    asm volatile("ldmatrix.sync.aligned.m8n8.x4.trans.shared.b16 {%0,%1,%2,%3}, [%4];"
                 : "=r"(d[0]), "=r"(d[1]), "=r"(d[2]), "=r"(d[3]) : "r"(a));
}
__device__ __forceinline__ void mma16816(float* c, const uint32_t* a,
                                         uint32_t b0, uint32_t b1) {
    asm volatile(
        "mma.sync.aligned.m16n8k16.row.col.f32.f16.f16.f32 "
        "{%0,%1,%2,%3}, {%4,%5,%6,%7}, {%8,%9}, {%0,%1,%2,%3};"
        : "+f"(c[0]), "+f"(c[1]), "+f"(c[2]), "+f"(c[3])
        : "r"(a[0]), "r"(a[1]), "r"(a[2]), "r"(a[3]), "r"(b0), "r"(b1));
}
__device__ __forceinline__ uint32_t pack2h(float x, float y) {
    __half2 h = __floats2half2_rn(x, y);
    return *reinterpret_cast<uint32_t*>(&h);
}

// ---------------------------------------------------------------------------
// Preprocessing: cast fp32 -> fp16
// ---------------------------------------------------------------------------
__global__ void cast_f32h(const float* __restrict__ src, __half* __restrict__ dst, int n4)
{
    for (int i = blockIdx.x * blockDim.x + threadIdx.x; i < n4;
         i += gridDim.x * blockDim.x) {
        float4 v = ((const float4*)src)[i];
        ((uint32_t*)dst)[2 * i]     = pack2h(v.x, v.y);
        ((uint32_t*)dst)[2 * i + 1] = pack2h(v.z, v.w);
    }
}

// ---------------------------------------------------------------------------
// GEMM: C[M,N] = A[M,K] @ W[N,K]^T + bias  (single-pass fp16, fp32 accum)
// 128x128 tile, 8 warps (2x4), warp 64x32, k-step 32, 2-stage cp.async.
// MODE 1: A=x  -> scatter q(*0.125)/k/v fp16 in [B,H,T,dk]
// MODE 0: A=y  -> fp32 out + bias
// ---------------------------------------------------------------------------
#define GROWB   80                          // 32 fp16 + pad
#define GTILEB  (128 * GROWB)               // 10240 B
#define GSTAGEB (2 * GTILEB)                // A, B
#define GSMEM   (2 * GSTAGEB)               // 40960 B

template <int MODE>
__global__ __launch_bounds__(256, 2) void gemm_mma(
    const float* __restrict__ bias, float* __restrict__ out)
{
    const __half* As = MODE ? g_x : g_y;
    const __half* Bs = MODE ? g_wa : g_wp;

    extern __shared__ char sm[];
    const int tid = threadIdx.x, wid = tid >> 5, lane = tid & 31;
    const int wm = wid >> 2, wn = wid & 3;
    const int m0 = blockIdx.y * 128, n0 = blockIdx.x * 128;

    float acc[4][4][4];
#pragma unroll
    for (int i = 0; i < 4; i++)
#pragma unroll
        for (int j = 0; j < 4; j++)
#pragma unroll
            for (int k = 0; k < 4; k++) acc[i][j][k] = 0.f;

    auto load_stage = [&](int st, int k0) {
        char* base = sm + st * GSTAGEB;
        const __half* srcs[2] = { As, Bs };
#pragma unroll
        for (int t = 0; t < 2; t++) {
            const int row0 = t ? n0 : m0;
#pragma unroll
            for (int i = 0; i < 2; i++) {
                const int id = tid + i * 256;        // 0..511
                const int r = id >> 2, c4 = id & 3;  // row, 16B chunk
                cpa16(sptr(base + t * GTILEB + r * GROWB + c4 * 16),
                      srcs[t] + (size_t)(row0 + r) * KD_ + k0 + c4 * 8);
            }
        }
    };

    load_stage(0, 0);
    CP_COMMIT();

    const int NSTEP = KD_ / 32;
    for (int kc = 0; kc < NSTEP; kc++) {
        if (kc + 1 < NSTEP) { load_stage((kc + 1) & 1, (kc + 1) * 32); CP_COMMIT(); CP_WAIT1(); }
        else                { CP_WAIT0(); }
        __syncthreads();

        char* Ab = sm + (kc & 1) * GSTAGEB;
        char* Bb = Ab + GTILEB;

#pragma unroll
        for (int kk = 0; kk < 2; kk++) {
            uint32_t af[4][4];
#pragma unroll
            for (int mi = 0; mi < 4; mi++) {
                const uint32_t off = (uint32_t)((wm * 64 + mi * 16 + (lane & 15)) * GROWB
                                                + (kk * 16 + (lane >> 4) * 8) * 2);
                ldsm4(af[mi], sptr(Ab + off));
            }
#pragma unroll
            for (int np = 0; np < 2; np++) {
                uint32_t bf[4];
                const uint32_t boff = (uint32_t)(
                    (wn * 32 + np * 16 + (lane & 7) + ((lane >> 4) << 3)) * GROWB
                    + (kk * 16 + ((lane >> 3) & 1) * 8) * 2);
                ldsm4(bf, sptr(Bb + boff));
#pragma unroll
                for (int mi = 0; mi < 4; mi++) {
                    mma16816(acc[mi][2 * np],     af[mi], bf[0], bf[1]);
                    mma16816(acc[mi][2 * np + 1], af[mi], bf[2], bf[3]);
                }
            }
        }
        __syncthreads();
    }

    // epilogue
#pragma unroll
    for (int mi = 0; mi < 4; mi++) {
        const int m = m0 + wm * 64 + mi * 16 + (lane >> 2);
#pragma unroll
        for (int ni = 0; ni < 4; ni++) {
            const int n = n0 + wn * 32 + ni * 8 + (lane & 3) * 2;
            const float b0 = bias[n], b1 = bias[n + 1];
            float v00 = acc[mi][ni][0] + b0, v01 = acc[mi][ni][1] + b1;  // row m
            float v10 = acc[mi][ni][2] + b0, v11 = acc[mi][ni][3] + b1;  // row m+8
            if (MODE == 0) {
                *(float2*)(out + (size_t)m * C_ + n)       = make_float2(v00, v01);
                *(float2*)(out + (size_t)(m + 8) * C_ + n) = make_float2(v10, v11);
            } else {
                const int sec = n >> 10;
                const int cc = n & 1023, h = cc >> 6, d = cc & 63;
                const int bb = m >> 11, t = m & 2047;
                const size_t base0 = ((size_t)((bb * H_ + h) * T_) + t) * DK_ + d;
                __half* dst;
                if (sec == 0) {
                    v00 *= 0.125f; v01 *= 0.125f; v10 *= 0.125f; v11 *= 0.125f;
                    dst = g_q;
                } else {
                    dst = (sec == 1) ? g_k : g_v;
                }
                *(uint32_t*)(dst + base0)           = pack2h(v00, v01);
                *(uint32_t*)(dst + base0 + 8 * DK_) = pack2h(v10, v11);
            }
        }
    }
}

// ---------------------------------------------------------------------------
// Flash attention (single-pass fp16). CTA: 128 queries x 1 head, 8 warps.
// Q preloaded to registers; K/V double-buffered cp.async.
// ---------------------------------------------------------------------------
#define AROWB   144                          // 64 fp16 + pad
#define ATILEB  (128 * AROWB)                // 18432 B
#define ASTAGEB (2 * ATILEB)                 // K + V
#define ASMEM   (2 * ASTAGEB)                // 73728 B

__global__ __launch_bounds__(256) void attn_mma()
{
    extern __shared__ char sm[];
    const int tid = threadIdx.x, wid = tid >> 5, lane = tid & 31;
    const int bh = blockIdx.x;
    const int q0 = blockIdx.y * 128;
    const size_t hb = (size_t)bh * T_ * DK_;

    // ---- stage Q into stage-0 area, read fragments to registers ----
#pragma unroll
    for (int i = 0; i < 4; i++) {
        const int id = tid + i * 256;
        const int r = id >> 3, c = id & 7;
        cpa16(sptr(sm + r * AROWB + c * 16), g_q + hb + (size_t)(q0 + r) * DK_ + c * 8);
    }
    CP_COMMIT();
    CP_WAIT0();
    __syncthreads();

    uint32_t qf[4][4];
#pragma unroll
    for (int kk = 0; kk < 4; kk++) {
        const uint32_t qoff = (uint32_t)((wid * 16 + (lane & 15)) * AROWB
                                         + (kk * 16 + (lane >> 4) * 8) * 2);
        ldsm4(qf[kk], sptr(sm + qoff));
    }
    __syncthreads();

    // ---- K/V pipeline ----
    auto load_kv = [&](int st, int kt) {
        char* base = sm + st * ASTAGEB;
#pragma unroll
        for (int i = 0; i < 4; i++) {
            const int id = tid + i * 256;
            const int r = id >> 3, c = id & 7;
            const size_t g = hb + (size_t)(kt * 128 + r) * DK_ + c * 8;
            const uint32_t so = r * AROWB + c * 16;
            cpa16(sptr(base + so),          g_k + g);
            cpa16(sptr(base + ATILEB + so), g_v + g);
        }
    };

    load_kv(0, 0); CP_COMMIT();
    load_kv(1, 1); CP_COMMIT();

    float o[8][4];
#pragma unroll
    for (int i = 0; i < 8; i++)
#pragma unroll
        for (int j = 0; j < 4; j++) o[i][j] = 0.f;
    float mrow0 = -1e30f, mrow1 = -1e30f, lrow0 = 0.f, lrow1 = 0.f;

    const int NT = T_ / 128;
    for (int kt = 0; kt < NT; kt++) {
        if (kt + 1 < NT) CP_WAIT1(); else CP_WAIT0();
        __syncthreads();
        char* Kb = sm + (kt & 1) * ASTAGEB;
        char* Vb = Kb + ATILEB;

        // S = Q K^T
        float s[16][4];
#pragma unroll
        for (int i = 0; i < 16; i++)
#pragma unroll
            for (int j = 0; j < 4; j++) s[i][j] = 0.f;

#pragma unroll
        for (int kk = 0; kk < 4; kk++) {
#pragma unroll
            for (int np = 0; np < 8; np++) {
                uint32_t kh[4];
                const uint32_t koff = (uint32_t)(
                    (np * 16 + (lane & 7) + ((lane >> 4) << 3)) * AROWB
                    + (kk * 16 + ((lane >> 3) & 1) * 8) * 2);
                ldsm4(kh, sptr(Kb + koff));
                mma16816(s[2 * np],     qf[kk], kh[0], kh[1]);
                mma16816(s[2 * np + 1], qf[kk], kh[2], kh[3]);
            }
        }

        // online softmax (rows lane>>2 and +8)
        float mx0 = -1e30f, mx1 = -1e30f;
#pragma unroll
        for (int nt = 0; nt < 16; nt++) {
            mx0 = fmaxf(mx0, fmaxf(s[nt][0], s[nt][1]));
            mx1 = fmaxf(mx1, fmaxf(s[nt][2], s[nt][3]));
        }
        mx0 = fmaxf(mx0, __shfl_xor_sync(0xffffffffu, mx0, 1));
        mx0 = fmaxf(mx0, __shfl_xor_sync(0xffffffffu, mx0, 2));
        mx1 = fmaxf(mx1, __shfl_xor_sync(0xffffffffu, mx1, 1));
        mx1 = fmaxf(mx1, __shfl_xor_sync(0xffffffffu, mx1, 2));
        const float mn0 = fmaxf(mrow0, mx0), mn1 = fmaxf(mrow1, mx1);
        const float cor0 = __expf(mrow0 - mn0), cor1 = __expf(mrow1 - mn1);
        mrow0 = mn0; mrow1 = mn1;
        float sum0 = 0.f, sum1 = 0.f;
#pragma unroll
        for (int nt = 0; nt < 16; nt++) {
            s[nt][0] = __expf(s[nt][0] - mn0); sum0 += s[nt][0];
            s[nt][1] = __expf(s[nt][1] - mn0); sum0 += s[nt][1];
            s[nt][2] = __expf(s[nt][2] - mn1); sum1 += s[nt][2];
            s[nt][3] = __expf(s[nt][3] - mn1); sum1 += s[nt][3];
        }
        sum0 += __shfl_xor_sync(0xffffffffu, sum0, 1);
        sum0 += __shfl_xor_sync(0xffffffffu, sum0, 2);
        sum1 += __shfl_xor_sync(0xffffffffu, sum1, 1);
        sum1 += __shfl_xor_sync(0xffffffffu, sum1, 2);
        lrow0 = lrow0 * cor0 + sum0;
        lrow1 = lrow1 * cor1 + sum1;
#pragma unroll
        for (int nt2 = 0; nt2 < 8; nt2++) {
            o[nt2][0] *= cor0; o[nt2][1] *= cor0;
            o[nt2][2] *= cor1; o[nt2][3] *= cor1;
        }

        // O += P V  (P rounded once to fp16)
#pragma unroll
        for (int j = 0; j < 8; j++) {
            uint32_t pf[4];
            pf[0] = pack2h(s[2 * j][0],     s[2 * j][1]);
            pf[1] = pack2h(s[2 * j][2],     s[2 * j][3]);
            pf[2] = pack2h(s[2 * j + 1][0], s[2 * j + 1][1]);
            pf[3] = pack2h(s[2 * j + 1][2], s[2 * j + 1][3]);
#pragma unroll
            for (int np = 0; np < 4; np++) {
                uint32_t vh[4];
                const uint32_t voff = (uint32_t)(
                    (j * 16 + (lane & 15)) * AROWB
                    + (np * 16 + (lane >> 4) * 8) * 2);
                ldsm4t(vh, sptr(Vb + voff));
                mma16816(o[2 * np],     pf, vh[0], vh[1]);
                mma16816(o[2 * np + 1], pf, vh[2], vh[3]);
            }
        }
        __syncthreads();
        if (kt + 2 < NT) { load_kv(kt & 1, kt + 2); CP_COMMIT(); }
    }

    // epilogue: normalize, write y fp16 [B,T,C]
    const float inv0 = 1.f / lrow0, inv1 = 1.f / lrow1;
    const int bb = bh >> 4, h = bh & 15;
    const int r0 = q0 + wid * 16 + (lane >> 2);
#pragma unroll
    for (int nt2 = 0; nt2 < 8; nt2++) {
        const int col = h * DK_ + nt2 * 8 + (lane & 3) * 2;
        const size_t i0 = (size_t)(bb * T_ + r0) * C_ + col;
        const size_t i1 = (size_t)(bb * T_ + r0 + 8) * C_ + col;
        *(uint32_t*)(g_y + i0) = pack2h(o[nt2][0] * inv0, o[nt2][1] * inv0);
        *(uint32_t*)(g_y + i1) = pack2h(o[nt2][2] * inv1, o[nt2][3] * inv1);
    }
}

// ---------------------------------------------------------------------------
extern "C" void kernel_launch(void* const* d_in, const int* in_sizes, int n_in,
                              void* d_out, int out_size)
{
    const float* x      = (const float*)d_in[0];
    const float* w_attn = (const float*)d_in[1];
    const float* b_attn = (const float*)d_in[2];
    const float* w_proj = (const float*)d_in[3];
    const float* b_proj = (const float*)d_in[4];
    float* out = (float*)d_out;

    static bool inited = false;
    if (!inited) {
        cudaFuncSetAttribute(gemm_mma<1>, cudaFuncAttributeMaxDynamicSharedMemorySize, GSMEM);
        cudaFuncSetAttribute(gemm_mma<0>, cudaFuncAttributeMaxDynamicSharedMemorySize, GSMEM);
        cudaFuncSetAttribute(attn_mma,    cudaFuncAttributeMaxDynamicSharedMemorySize, ASMEM);
        inited = true;
    }

    __half *xh, *wa, *wp;
    cudaGetSymbolAddress((void**)&xh, g_x);
    cudaGetSymbolAddress((void**)&wa, g_wa);
    cudaGetSymbolAddress((void**)&wp, g_wp);

    // 0) preprocessing: fp32 -> fp16 casts
    cast_f32h<<<2048, 256>>>(x,      xh, (M_ * C_) / 4);
    cast_f32h<<<1024, 256>>>(w_attn, wa, (3 * C_ * C_) / 4);
    cast_f32h<<<512,  256>>>(w_proj, wp, (C_ * C_) / 4);

    // 1) QKV projection -> q(*0.125)/k/v fp16 [B,H,T,dk]
    gemm_mma<1><<<dim3((3 * C_) / 128, M_ / 128), 256, GSMEM>>>(b_attn, nullptr);

    // 2) flash attention -> y fp16 [B,T,C]
    attn_mma<<<dim3(B_ * H_, T_ / 128), 256, ASMEM>>>();

    // 3) output projection -> out (fp32)
    gemm_mma<0><<<dim3(C_ / 128, M_ / 128), 256, GSMEM>>>(b_proj, out);
}

// round 6
// speedup vs baseline: 8.6411x; 1.0176x over previous
#include <cuda_runtime.h>
#include <cuda_fp16.h>
#include <cstdint>

#define B_  4
#define T_  2048
#define C_  1024
#define H_  16
#define DK_ 64
#define M_  (B_ * T_)      // 8192
#define KD_ 1024

// ---------------------------------------------------------------------------
// Scratch (static __device__ arrays)
// ---------------------------------------------------------------------------
__device__ __half g_x [(size_t)M_ * C_];
__device__ __half g_wa[(size_t)3 * C_ * C_];
__device__ __half g_wp[(size_t)C_ * C_];
__device__ __half g_q [(size_t)M_ * C_];   // [B,H,T,dk], pre-scaled by 0.125
__device__ __half g_k [(size_t)M_ * C_];   // [B,H,T,dk]
__device__ __half g_v [(size_t)M_ * C_];
__device__ __half g_y [(size_t)M_ * C_];   // [B,T,C]

// ---------------------------------------------------------------------------
// Helpers (baseline PTX: mma.sync f16 / ldmatrix / cp.async)
// ---------------------------------------------------------------------------
__device__ __forceinline__ uint32_t sptr(const void* p) {
    return (uint32_t)__cvta_generic_to_shared(p);
}
__device__ __forceinline__ void cpa16(uint32_t s, const void* g) {
    asm volatile("cp.async.cg.shared.global [%0], [%1], 16;" :: "r"(s), "l"(g));
}
#define CP_COMMIT() asm volatile("cp.async.commit_group;" ::: "memory")
#define CP_WAIT0()  asm volatile("cp.async.wait_group 0;" ::: "memory")
#define CP_WAIT1()  asm volatile("cp.async.wait_group 1;" ::: "memory")

__device__ __forceinline__ void ldsm4(uint32_t* d, uint32_t a) {
    asm volatile("ldmatrix.sync.aligned.m8n8.x4.shared.b16 {%0,%1,%2,%3}, [%4];"
                 : "=r"(d[0]), "=r"(d[1]), "=r"(d[2]), "=r"(d[3]) : "r"(a));
}
__device__ __forceinline__ void ldsm4t(uint32_t* d, uint32_t a) {
    asm volatile("ldmatrix.sync.aligned.m8n8.x4.trans.shared.b16 {%0,%1,%2,%3}, [%4];"
                 : "=r"(d[0]), "=r"(d[1]), "=r"(d[2]), "=r"(d[3]) : "r"(a));
}
__device__ __forceinline__ void mma16816(float* c, const uint32_t* a,
                                         uint32_t b0, uint32_t b1) {
    asm volatile(
        "mma.sync.aligned.m16n8k16.row.col.f32.f16.f16.f32 "
        "{%0,%1,%2,%3}, {%4,%5,%6,%7}, {%8,%9}, {%0,%1,%2,%3};"
        : "+f"(c[0]), "+f"(c[1]), "+f"(c[2]), "+f"(c[3])
        : "r"(a[0]), "r"(a[1]), "r"(a[2]), "r"(a[3]), "r"(b0), "r"(b1));
}
__device__ __forceinline__ uint32_t pack2h(float x, float y) {
    __half2 h = __floats2half2_rn(x, y);
    return *reinterpret_cast<uint32_t*>(&h);
}

// ---------------------------------------------------------------------------
// Preprocessing: all three fp32 -> fp16 casts in one grid-stride kernel
// ---------------------------------------------------------------------------
#define N4_X  ((M_ * C_) / 4)            // 2097152
#define N4_WA ((3 * C_ * C_) / 4)        // 786432
#define N4_WP ((C_ * C_) / 4)            // 262144
#define N4_TOT (N4_X + N4_WA + N4_WP)

__global__ void cast_all(const float* __restrict__ x, const float* __restrict__ wa,
                         const float* __restrict__ wp)
{
    for (int i = blockIdx.x * blockDim.x + threadIdx.x; i < N4_TOT;
         i += gridDim.x * blockDim.x) {
        const float* src;
        __half* dst;
        int j = i;
        if (j < N4_X)                 { src = x;  dst = g_x; }
        else if ((j -= N4_X) < N4_WA) { src = wa; dst = g_wa; }
        else                          { j -= N4_WA; src = wp; dst = g_wp; }
        float4 v = ((const float4*)src)[j];
        ((uint32_t*)dst)[2 * j]     = pack2h(v.x, v.y);
        ((uint32_t*)dst)[2 * j + 1] = pack2h(v.z, v.w);
    }
}

// ---------------------------------------------------------------------------
// GEMM: C[M,N] = A[M,K] @ W[N,K]^T + bias  (fp16 in, fp32 accum)
// CTA tile 128x256, 8 warps (2x4), warp tile 64x64, BK=64, 2-stage cp.async.
// MODE 1: A=x  -> scatter q(*0.125)/k/v fp16 in [B,H,T,dk]
// MODE 0: A=y  -> fp32 out + bias
// ---------------------------------------------------------------------------
#define GROWB   144                         // 64 fp16 (128B) + 16B pad
#define GATILEB (128 * GROWB)               // 18432 B
#define GBTILEB (256 * GROWB)               // 36864 B
#define GSTAGEB (GATILEB + GBTILEB)         // 55296 B
#define GSMEM   (2 * GSTAGEB)               // 110592 B

template <int MODE>
__global__ __launch_bounds__(256, 1) void gemm_mma(
    const float* __restrict__ bias, float* __restrict__ out)
{
    const __half* As = MODE ? g_x : g_y;
    const __half* Bs = MODE ? g_wa : g_wp;

    extern __shared__ char sm[];
    const int tid = threadIdx.x, wid = tid >> 5, lane = tid & 31;
    const int wm = wid >> 2, wn = wid & 3;
    const int m0 = blockIdx.y * 128, n0 = blockIdx.x * 256;

    float acc[4][8][4];
#pragma unroll
    for (int i = 0; i < 4; i++)
#pragma unroll
        for (int j = 0; j < 8; j++)
#pragma unroll
            for (int k = 0; k < 4; k++) acc[i][j][k] = 0.f;

    auto load_stage = [&](int st, int k0) {
        char* base = sm + st * GSTAGEB;
        // A: 128 rows x 8 chunks = 1024
#pragma unroll
        for (int i = 0; i < 4; i++) {
            const int id = tid + i * 256;
            const int r = id >> 3, c = id & 7;
            cpa16(sptr(base + r * GROWB + c * 16),
                  As + (size_t)(m0 + r) * KD_ + k0 + c * 8);
        }
        // B: 256 rows x 8 chunks = 2048
#pragma unroll
        for (int i = 0; i < 8; i++) {
            const int id = tid + i * 256;
            const int r = id >> 3, c = id & 7;
            cpa16(sptr(base + GATILEB + r * GROWB + c * 16),
                  Bs + (size_t)(n0 + r) * KD_ + k0 + c * 8);
        }
    };

    load_stage(0, 0);
    CP_COMMIT();

    const int NSTEP = KD_ / 64;   // 16
    for (int kc = 0; kc < NSTEP; kc++) {
        if (kc + 1 < NSTEP) { load_stage((kc + 1) & 1, (kc + 1) * 64); CP_COMMIT(); CP_WAIT1(); }
        else                { CP_WAIT0(); }
        __syncthreads();

        char* Ab = sm + (kc & 1) * GSTAGEB;
        char* Bb = Ab + GATILEB;

#pragma unroll
        for (int kk = 0; kk < 4; kk++) {
            uint32_t af[4][4];
#pragma unroll
            for (int mi = 0; mi < 4; mi++) {
                const uint32_t off = (uint32_t)((wm * 64 + mi * 16 + (lane & 15)) * GROWB
                                                + (kk * 16 + (lane >> 4) * 8) * 2);
                ldsm4(af[mi], sptr(Ab + off));
            }
#pragma unroll
            for (int nj = 0; nj < 4; nj++) {
                uint32_t bf[4];
                const uint32_t boff = (uint32_t)(
                    (wn * 64 + nj * 16 + (lane & 7) + ((lane >> 4) << 3)) * GROWB
                    + (kk * 16 + ((lane >> 3) & 1) * 8) * 2);
                ldsm4(bf, sptr(Bb + boff));
#pragma unroll
                for (int mi = 0; mi < 4; mi++) {
                    mma16816(acc[mi][2 * nj],     af[mi], bf[0], bf[1]);
                    mma16816(acc[mi][2 * nj + 1], af[mi], bf[2], bf[3]);
                }
            }
        }
        __syncthreads();
    }

    // epilogue
#pragma unroll
    for (int mi = 0; mi < 4; mi++) {
        const int m = m0 + wm * 64 + mi * 16 + (lane >> 2);
#pragma unroll
        for (int ni = 0; ni < 8; ni++) {
            const int n = n0 + wn * 64 + (ni >> 1) * 16 + (ni & 1) * 8 + (lane & 3) * 2;
            const float b0 = bias[n], b1 = bias[n + 1];
            float v00 = acc[mi][ni][0] + b0, v01 = acc[mi][ni][1] + b1;  // row m
            float v10 = acc[mi][ni][2] + b0, v11 = acc[mi][ni][3] + b1;  // row m+8
            if (MODE == 0) {
                *(float2*)(out + (size_t)m * C_ + n)       = make_float2(v00, v01);
                *(float2*)(out + (size_t)(m + 8) * C_ + n) = make_float2(v10, v11);
            } else {
                const int sec = n >> 10;
                const int cc = n & 1023, h = cc >> 6, d = cc & 63;
                const int bb = m >> 11, t = m & 2047;
                const size_t base0 = ((size_t)((bb * H_ + h) * T_) + t) * DK_ + d;
                __half* dst;
                if (sec == 0) {
                    v00 *= 0.125f; v01 *= 0.125f; v10 *= 0.125f; v11 *= 0.125f;
                    dst = g_q;
                } else {
                    dst = (sec == 1) ? g_k : g_v;
                }
                *(uint32_t*)(dst + base0)           = pack2h(v00, v01);
                *(uint32_t*)(dst + base0 + 8 * DK_) = pack2h(v10, v11);
            }
        }
    }
}

// ---------------------------------------------------------------------------
// Flash attention (single-pass fp16). CTA: 128 queries x 1 head, 8 warps.
// Q preloaded to registers; K/V double-buffered cp.async.
// ---------------------------------------------------------------------------
#define AROWB   144                          // 64 fp16 + pad
#define ATILEB  (128 * AROWB)                // 18432 B
#define ASTAGEB (2 * ATILEB)                 // K + V
#define ASMEM   (2 * ASTAGEB)                // 73728 B

__global__ __launch_bounds__(256) void attn_mma()
{
    extern __shared__ char sm[];
    const int tid = threadIdx.x, wid = tid >> 5, lane = tid & 31;
    const int bh = blockIdx.x;
    const int q0 = blockIdx.y * 128;
    const size_t hb = (size_t)bh * T_ * DK_;

    // ---- stage Q into stage-0 area, read fragments to registers ----
#pragma unroll
    for (int i = 0; i < 4; i++) {
        const int id = tid + i * 256;
        const int r = id >> 3, c = id & 7;
        cpa16(sptr(sm + r * AROWB + c * 16), g_q + hb + (size_t)(q0 + r) * DK_ + c * 8);
    }
    CP_COMMIT();
    CP_WAIT0();
    __syncthreads();

    uint32_t qf[4][4];
#pragma unroll
    for (int kk = 0; kk < 4; kk++) {
        const uint32_t qoff = (uint32_t)((wid * 16 + (lane & 15)) * AROWB
                                         + (kk * 16 + (lane >> 4) * 8) * 2);
        ldsm4(qf[kk], sptr(sm + qoff));
    }
    __syncthreads();

    // ---- K/V pipeline ----
    auto load_kv = [&](int st, int kt) {
        char* base = sm + st * ASTAGEB;
#pragma unroll
        for (int i = 0; i < 4; i++) {
            const int id = tid + i * 256;
            const int r = id >> 3, c = id & 7;
            const size_t g = hb + (size_t)(kt * 128 + r) * DK_ + c * 8;
            const uint32_t so = r * AROWB + c * 16;
            cpa16(sptr(base + so),          g_k + g);
            cpa16(sptr(base + ATILEB + so), g_v + g);
        }
    };

    load_kv(0, 0); CP_COMMIT();
    load_kv(1, 1); CP_COMMIT();

    float o[8][4];
#pragma unroll
    for (int i = 0; i < 8; i++)
#pragma unroll
        for (int j = 0; j < 4; j++) o[i][j] = 0.f;
    float mrow0 = -1e30f, mrow1 = -1e30f, lrow0 = 0.f, lrow1 = 0.f;

    const int NT = T_ / 128;
    for (int kt = 0; kt < NT; kt++) {
        if (kt + 1 < NT) CP_WAIT1(); else CP_WAIT0();
        __syncthreads();
        char* Kb = sm + (kt & 1) * ASTAGEB;
        char* Vb = Kb + ATILEB;

        // S = Q K^T
        float s[16][4];
#pragma unroll
        for (int i = 0; i < 16; i++)
#pragma unroll
            for (int j = 0; j < 4; j++) s[i][j] = 0.f;

#pragma unroll
        for (int kk = 0; kk < 4; kk++) {
#pragma unroll
            for (int np = 0; np < 8; np++) {
                uint32_t kh[4];
                const uint32_t koff = (uint32_t)(
                    (np * 16 + (lane & 7) + ((lane >> 4) << 3)) * AROWB
                    + (kk * 16 + ((lane >> 3) & 1) * 8) * 2);
                ldsm4(kh, sptr(Kb + koff));
                mma16816(s[2 * np],     qf[kk], kh[0], kh[1]);
                mma16816(s[2 * np + 1], qf[kk], kh[2], kh[3]);
            }
        }

        // online softmax (rows lane>>2 and +8)
        float mx0 = -1e30f, mx1 = -1e30f;
#pragma unroll
        for (int nt = 0; nt < 16; nt++) {
            mx0 = fmaxf(mx0, fmaxf(s[nt][0], s[nt][1]));
            mx1 = fmaxf(mx1, fmaxf(s[nt][2], s[nt][3]));
        }
        mx0 = fmaxf(mx0, __shfl_xor_sync(0xffffffffu, mx0, 1));
        mx0 = fmaxf(mx0, __shfl_xor_sync(0xffffffffu, mx0, 2));
        mx1 = fmaxf(mx1, __shfl_xor_sync(0xffffffffu, mx1, 1));
        mx1 = fmaxf(mx1, __shfl_xor_sync(0xffffffffu, mx1, 2));
        const float mn0 = fmaxf(mrow0, mx0), mn1 = fmaxf(mrow1, mx1);
        const float cor0 = __expf(mrow0 - mn0), cor1 = __expf(mrow1 - mn1);
        mrow0 = mn0; mrow1 = mn1;
        float sum0 = 0.f, sum1 = 0.f;
#pragma unroll
        for (int nt = 0; nt < 16; nt++) {
            s[nt][0] = __expf(s[nt][0] - mn0); sum0 += s[nt][0];
            s[nt][1] = __expf(s[nt][1] - mn0); sum0 += s[nt][1];
            s[nt][2] = __expf(s[nt][2] - mn1); sum1 += s[nt][2];
            s[nt][3] = __expf(s[nt][3] - mn1); sum1 += s[nt][3];
        }
        sum0 += __shfl_xor_sync(0xffffffffu, sum0, 1);
        sum0 += __shfl_xor_sync(0xffffffffu, sum0, 2);
        sum1 += __shfl_xor_sync(0xffffffffu, sum1, 1);
        sum1 += __shfl_xor_sync(0xffffffffu, sum1, 2);
        lrow0 = lrow0 * cor0 + sum0;
        lrow1 = lrow1 * cor1 + sum1;
#pragma unroll
        for (int nt2 = 0; nt2 < 8; nt2++) {
            o[nt2][0] *= cor0; o[nt2][1] *= cor0;
            o[nt2][2] *= cor1; o[nt2][3] *= cor1;
        }

        // O += P V  (P rounded once to fp16)
#pragma unroll
        for (int j = 0; j < 8; j++) {
            uint32_t pf[4];
            pf[0] = pack2h(s[2 * j][0],     s[2 * j][1]);
            pf[1] = pack2h(s[2 * j][2],     s[2 * j][3]);
            pf[2] = pack2h(s[2 * j + 1][0], s[2 * j + 1][1]);
            pf[3] = pack2h(s[2 * j + 1][2], s[2 * j + 1][3]);
#pragma unroll
            for (int np = 0; np < 4; np++) {
                uint32_t vh[4];
                const uint32_t voff = (uint32_t)(
                    (j * 16 + (lane & 15)) * AROWB
                    + (np * 16 + (lane >> 4) * 8) * 2);
                ldsm4t(vh, sptr(Vb + voff));
                mma16816(o[2 * np],     pf, vh[0], vh[1]);
                mma16816(o[2 * np + 1], pf, vh[2], vh[3]);
            }
        }
        __syncthreads();
        if (kt + 2 < NT) { load_kv(kt & 1, kt + 2); CP_COMMIT(); }
    }

    // epilogue: normalize, write y fp16 [B,T,C]
    const float inv0 = 1.f / lrow0, inv1 = 1.f / lrow1;
    const int bb = bh >> 4, h = bh & 15;
    const int r0 = q0 + wid * 16 + (lane >> 2);
#pragma unroll
    for (int nt2 = 0; nt2 < 8; nt2++) {
        const int col = h * DK_ + nt2 * 8 + (lane & 3) * 2;
        const size_t i0 = (size_t)(bb * T_ + r0) * C_ + col;
        const size_t i1 = (size_t)(bb * T_ + r0 + 8) * C_ + col;
        *(uint32_t*)(g_y + i0) = pack2h(o[nt2][0] * inv0, o[nt2][1] * inv0);
        *(uint32_t*)(g_y + i1) = pack2h(o[nt2][2] * inv1, o[nt2][3] * inv1);
    }
}

// ---------------------------------------------------------------------------
extern "C" void kernel_launch(void* const* d_in, const int* in_sizes, int n_in,
                              void* d_out, int out_size)
{
    const float* x      = (const float*)d_in[0];
    const float* w_attn = (const float*)d_in[1];
    const float* b_attn = (const float*)d_in[2];
    const float* w_proj = (const float*)d_in[3];
    const float* b_proj = (const float*)d_in[4];
    float* out = (float*)d_out;

    static bool inited = false;
    if (!inited) {
        cudaFuncSetAttribute(gemm_mma<1>, cudaFuncAttributeMaxDynamicSharedMemorySize, GSMEM);
        cudaFuncSetAttribute(gemm_mma<0>, cudaFuncAttributeMaxDynamicSharedMemorySize, GSMEM);
        cudaFuncSetAttribute(attn_mma,    cudaFuncAttributeMaxDynamicSharedMemorySize, ASMEM);
        inited = true;
    }

    // 0) preprocessing: fp32 -> fp16 casts (one kernel)
    cast_all<<<2048, 256>>>(x, w_attn, w_proj);

    // 1) QKV projection -> q(*0.125)/k/v fp16 [B,H,T,dk]
    gemm_mma<1><<<dim3((3 * C_) / 256, M_ / 128), 256, GSMEM>>>(b_attn, nullptr);

    // 2) flash attention -> y fp16 [B,T,C]
    attn_mma<<<dim3(B_ * H_, T_ / 128), 256, ASMEM>>>();

    // 3) output projection -> out (fp32)
    gemm_mma<0><<<dim3(C_ / 256, M_ / 128), 256, GSMEM>>>(b_proj, out);
}